// round 17
// baseline (speedup 1.0000x reference)
#include <cuda_runtime.h>
#include <cuda_bf16.h>

#define FIVE_K 6
#define OUT_N  512
#define IN_N   1024
#define HID_N  32
#define B_N    256

typedef unsigned long long ull;

// topk results: 6 indices per output unit (allocation-free scratch)
__device__ int g_idx[OUT_N * FIVE_K];

// ---------------------------------------------------------------------------
// f32x2 packed helpers (FFMA2 — ptxas never emits these from C++)
// ---------------------------------------------------------------------------
__device__ __forceinline__ ull pack2(float a, float b) {
    ull r;
    asm("mov.b64 %0, {%1, %2};"
        : "=l"(r) : "r"(__float_as_uint(a)), "r"(__float_as_uint(b)));
    return r;
}
__device__ __forceinline__ ull pdup(float a) {
    ull r;
    asm("mov.b64 %0, {%1, %1};" : "=l"(r) : "r"(__float_as_uint(a)));
    return r;
}
__device__ __forceinline__ void fma2(ull& d, ull a, ull b) {
    asm("fma.rn.f32x2 %0, %1, %2, %0;" : "+l"(d) : "l"(a), "l"(b));
}
__device__ __forceinline__ void unpack2(ull v, float& lo, float& hi) {
    unsigned ulo, uhi;
    asm("mov.b64 {%0, %1}, %2;" : "=r"(ulo), "=r"(uhi) : "l"(v));
    lo = __uint_as_float(ulo);
    hi = __uint_as_float(uhi);
}

// cp.async: 16B global -> shared, zero register footprint for the data
__device__ __forceinline__ unsigned smem_u32(const void* p) {
    return (unsigned)__cvta_generic_to_shared(p);
}
__device__ __forceinline__ void cp_async16(unsigned dst, const void* src) {
    asm volatile("cp.async.cg.shared.global [%0], [%1], 16;"
                 :: "r"(dst), "l"(src));
}
__device__ __forceinline__ void cp_async_wait_all() {
    asm volatile("cp.async.commit_group;");
    asm volatile("cp.async.wait_group 0;" ::: "memory");
}

// ---------------------------------------------------------------------------
// topk machinery: 64-bit keys (orderable_float << 10) | (1023 - idx)
// (validated rel_err 0.0 since R4 — unchanged)
// ---------------------------------------------------------------------------
__device__ __forceinline__ ull mk_key(float x, int gi) {
    unsigned u = __float_as_uint(x);
    unsigned ord = (u & 0x80000000u) ? ~u : (u | 0x80000000u);
    return ((ull)ord << 10) | (ull)(1023 - gi);
}
__device__ __forceinline__ void cas(ull& a, ull& b) {
    ull hi = a > b ? a : b;
    ull lo = a > b ? b : a;
    a = hi; b = lo;
}
__device__ __forceinline__ ull mx(ull a, ull b) { return a > b ? a : b; }

__device__ __forceinline__ void sort6(ull* t) {
    cas(t[0], t[1]); cas(t[2], t[3]); cas(t[4], t[5]);
    cas(t[0], t[2]); cas(t[1], t[3]);
    cas(t[1], t[2]);
    cas(t[0], t[4]); cas(t[1], t[5]);
    cas(t[2], t[4]); cas(t[3], t[5]);
    cas(t[1], t[2]); cas(t[3], t[4]);
}
__device__ __forceinline__ void merge6(ull* a, const ull* b) {
    ull t[6];
    t[0] = mx(a[0], b[5]); t[1] = mx(a[1], b[4]); t[2] = mx(a[2], b[3]);
    t[3] = mx(a[3], b[2]); t[4] = mx(a[4], b[1]); t[5] = mx(a[5], b[0]);
    sort6(t);
#pragma unroll
    for (int q = 0; q < 6; q++) a[q] = t[q];
}
__device__ __forceinline__ void sort4(ull& a0, ull& a1, ull& a2, ull& a3) {
    cas(a0, a1); cas(a2, a3); cas(a0, a2); cas(a1, a3); cas(a1, a2);
}

// ---------------------------------------------------------------------------
// Kernel 1: standalone top-6. One block (128 threads) per mask row.
// (R10's validated topk logic; unconstrained registers)
// ---------------------------------------------------------------------------
__global__ void topk6_kernel(const float* __restrict__ mask)
{
    __shared__ ull sLists[4][6];

    const int o    = blockIdx.x;
    const int tid  = threadIdx.x;
    const int warp = tid >> 5;
    const int lane = tid & 31;

    const float4* mk4 = reinterpret_cast<const float4*>(mask + o * IN_N);
    float4 m0 = mk4[tid], m1 = mk4[tid + 128];

    ull a[6], bl[6];
    {
        ull k0 = mk_key(m0.x, 4 * tid + 0);
        ull k1 = mk_key(m0.y, 4 * tid + 1);
        ull k2 = mk_key(m0.z, 4 * tid + 2);
        ull k3 = mk_key(m0.w, 4 * tid + 3);
        ull k4 = mk_key(m1.x, 4 * (tid + 128) + 0);
        ull k5 = mk_key(m1.y, 4 * (tid + 128) + 1);
        ull k6 = mk_key(m1.z, 4 * (tid + 128) + 2);
        ull k7 = mk_key(m1.w, 4 * (tid + 128) + 3);
        sort4(k0, k1, k2, k3);
        sort4(k4, k5, k6, k7);
        a[0]  = k0; a[1]  = k1; a[2]  = k2; a[3]  = k3; a[4]  = 0; a[5]  = 0;
        bl[0] = k4; bl[1] = k5; bl[2] = k6; bl[3] = k7; bl[4] = 0; bl[5] = 0;
        merge6(a, bl);
    }
#pragma unroll
    for (int off = 16; off >= 1; off >>= 1) {
#pragma unroll
        for (int j = 0; j < 6; j++)
            bl[j] = __shfl_xor_sync(0xFFFFFFFFu, a[j], off);
        merge6(a, bl);
    }
    if (lane == 0) {
#pragma unroll
        for (int j = 0; j < 6; j++) sLists[warp][j] = a[j];
    }
    __syncthreads();

    if (warp == 0) {
#pragma unroll
        for (int w = 1; w < 4; w++) {
#pragma unroll
            for (int j = 0; j < 6; j++) bl[j] = sLists[w][j];
            merge6(a, bl);
        }
        if (lane == 0) {
#pragma unroll
            for (int j = 0; j < 6; j++)
                g_idx[o * FIVE_K + j] = 1023 - (int)(a[j] & 1023ull);
        }
    }
}

// ---------------------------------------------------------------------------
// Kernel 2: MLP. TWO blocks (128 threads) per unit o (grid 1024); one batch
// element per thread (E=1) — R6's exact inline body (measured clean: 96 regs
// under (128,5) cap 102). cp.async weight staging + g_idx read REDUCE
// prologue pressure vs R6's proven compile. 5 blocks/SM = 20 warps.
// ---------------------------------------------------------------------------
__global__ __launch_bounds__(128, 5)
void mlp_kernel(const float* __restrict__ inputs,
                const float* __restrict__ W1,
                const float* __restrict__ W2,
                const float* __restrict__ W3,
                const float* __restrict__ W4,
                float* __restrict__ out)
{
    __shared__ float sW1[FIVE_K * HID_N];
    __shared__ float sW2[HID_N * HID_N];
    __shared__ float sW3[HID_N * HID_N];
    __shared__ float sW4[HID_N];
    __shared__ int   sIdx[FIVE_K];

    const int o   = blockIdx.x >> 1;
    const int b   = ((blockIdx.x & 1) << 7) + threadIdx.x;  // my batch element
    const int tid = threadIdx.x;

    // -- stage dense weights via cp.async (zero register footprint) --
    {
        const char* w2p = reinterpret_cast<const char*>(W2 + o * HID_N * HID_N);
        const char* w3p = reinterpret_cast<const char*>(W3 + o * HID_N * HID_N);
        unsigned s2 = smem_u32(sW2), s3 = smem_u32(sW3);
        cp_async16(s2 + tid * 16,          w2p + tid * 16);
        cp_async16(s2 + (tid + 128) * 16,  w2p + (tid + 128) * 16);
        cp_async16(s3 + tid * 16,          w3p + tid * 16);
        cp_async16(s3 + (tid + 128) * 16,  w3p + (tid + 128) * 16);
        if (tid < 8)
            cp_async16(smem_u32(sW4) + tid * 16,
                       reinterpret_cast<const char*>(W4 + o * HID_N) + tid * 16);
    }

    if (tid < FIVE_K) sIdx[tid] = g_idx[o * FIVE_K + tid];

    cp_async_wait_all();
    __syncthreads();     // sIdx + weights visible

    // -- W1 rows for the 6 picked features + my 6 input values --
#pragma unroll
    for (int t = tid; t < FIVE_K * HID_N; t += 128) {
        int j = t >> 5, k = t & 31;
        sW1[t] = W1[(o * IN_N + sIdx[j]) * HID_N + k];
    }
    float x[FIVE_K];
#pragma unroll
    for (int j = 0; j < FIVE_K; j++)
        x[j] = inputs[b * IN_N + sIdx[j]];
    __syncthreads();

    // ---------------- MLP: one element, packed f32x2 (R6 body) ----------------
    float h[HID_N];
    ull acc[16];

    // layer 1: 6 -> 32
#pragma unroll
    for (int q = 0; q < 16; q++) acc[q] = 0ull;
#pragma unroll
    for (int r = 0; r < FIVE_K; r++) {
        const ulonglong2* wr = reinterpret_cast<const ulonglong2*>(sW1 + r * HID_N);
        ull d = pdup(x[r]);
#pragma unroll
        for (int q = 0; q < 8; q++) {
            ulonglong2 w = wr[q];
            fma2(acc[2 * q],     d, w.x);
            fma2(acc[2 * q + 1], d, w.y);
        }
    }
#pragma unroll
    for (int q = 0; q < 16; q++) {
        float lo, hi; unpack2(acc[q], lo, hi);
        h[2 * q]     = fmaxf(lo, 0.f);
        h[2 * q + 1] = fmaxf(hi, 0.f);
    }

    // layer 2: 32 -> 32
#pragma unroll
    for (int q = 0; q < 16; q++) acc[q] = 0ull;
#pragma unroll
    for (int r = 0; r < HID_N; r++) {
        const ulonglong2* wr = reinterpret_cast<const ulonglong2*>(sW2 + r * HID_N);
        ull d = pdup(h[r]);
#pragma unroll
        for (int q = 0; q < 8; q++) {
            ulonglong2 w = wr[q];
            fma2(acc[2 * q],     d, w.x);
            fma2(acc[2 * q + 1], d, w.y);
        }
    }
#pragma unroll
    for (int q = 0; q < 16; q++) {
        float lo, hi; unpack2(acc[q], lo, hi);
        h[2 * q]     = fmaxf(lo, 0.f);
        h[2 * q + 1] = fmaxf(hi, 0.f);
    }

    // layer 3: 32 -> 32
#pragma unroll
    for (int q = 0; q < 16; q++) acc[q] = 0ull;
#pragma unroll
    for (int r = 0; r < HID_N; r++) {
        const ulonglong2* wr = reinterpret_cast<const ulonglong2*>(sW3 + r * HID_N);
        ull d = pdup(h[r]);
#pragma unroll
        for (int q = 0; q < 8; q++) {
            ulonglong2 w = wr[q];
            fma2(acc[2 * q],     d, w.x);
            fma2(acc[2 * q + 1], d, w.y);
        }
    }
#pragma unroll
    for (int q = 0; q < 16; q++) {
        float lo, hi; unpack2(acc[q], lo, hi);
        h[2 * q]     = fmaxf(lo, 0.f);
        h[2 * q + 1] = fmaxf(hi, 0.f);
    }

    // layer 4: 32 -> 1, sign (sigmoid(z) >= 0.5 <=> z >= 0)
    ull s = 0ull;
    const ull* w4p = reinterpret_cast<const ull*>(sW4);
#pragma unroll
    for (int p = 0; p < 16; p++)
        fma2(s, pack2(h[2 * p], h[2 * p + 1]), w4p[p]);
    float l0, l1;
    unpack2(s, l0, l1);
    float z = l0 + l1;

    out[b * OUT_N + o] = (z >= 0.f) ? 1.f : -1.f;
}

// ---------------------------------------------------------------------------
extern "C" void kernel_launch(void* const* d_in, const int* in_sizes, int n_in,
                              void* d_out, int out_size)
{
    const float* inputs = (const float*)d_in[0];  // (B, IN)
    const float* mask   = (const float*)d_in[1];  // (OUT, IN)
    const float* W1     = (const float*)d_in[2];  // (OUT, IN, HID)
    const float* W2     = (const float*)d_in[3];  // (OUT, HID, HID)
    const float* W3     = (const float*)d_in[4];  // (OUT, HID, HID)
    const float* W4     = (const float*)d_in[5];  // (OUT, HID, 1)
    float* out = (float*)d_out;                   // (B, OUT)

    topk6_kernel<<<OUT_N, 128>>>(mask);
    mlp_kernel<<<OUT_N * 2, 128>>>(inputs, W1, W2, W3, W4, out);
}